// round 8
// baseline (speedup 1.0000x reference)
#include <cuda_runtime.h>

// Problem constants (fixed by the dataset)
#define Bc   2
#define Sc   4096
#define Hc   12
#define Gc   64
#define Wc   513
#define WGc  577      // G + W
#define HALF 256      // W/2
#define BSc  (Bc * Sc)

#define N_SPLIT         8            // s-splits per 128-wide i-tile
#define N_TILES         (Bc * 32)    // 128-wide i-tiles
#define N_LOCAL_BLOCKS  (N_TILES * N_SPLIT)   // 512
#define N_GCHUNK        96           // row-chunks per batch for global sums
#define N_GLOBAL_BLOCKS (Bc * N_GCHUNK)       // 192

// Scratch (plain stores only -> no init kernel, replay-deterministic)
__device__ float g_local_part[N_SPLIT * BSc];        // per-split local partials
__device__ float g_glob_part[N_GLOBAL_BLOCKS * Gc];  // per-chunk global partials

// ---------------------------------------------------------------------------
// Fused main pass: reads all 227 MB of probs exactly once.
//
// Local role (blocks 0..511), gather formulation:
//   local_sum[b,i] = sum_{s} sum_h probs[b,s,h, 320+i-s],  c in [64,577)
//   Block owns 128 consecutive i (4 warps side-by-side) -> for each (s,h)
//   the block loads a CONTIGUOUS 512B span (minimal sector overfetch).
//   8 warps = 4 i-subtiles x 2 s-subgroups; 8 s-splits across blocks.
// Global role (blocks 512..703):
//   global_sum[b,c] = sum_{s,h} probs[b,s,h,c], c < 64
// ---------------------------------------------------------------------------
__global__ __launch_bounds__(256) void main_kernel(
    const float* __restrict__ probs, const float* __restrict__ mask)
{
    if (blockIdx.x < N_LOCAL_BLOCKS) {
        const int tile  = blockIdx.x >> 3;    // 0..63
        const int split = blockIdx.x & 7;     // 0..7
        const int w     = threadIdx.x >> 5;   // 0..7
        const int lane  = threadIdx.x & 31;
        const int iw    = w & 3;              // i-subtile within block
        const int sg    = w >> 2;             // s-subgroup (0,1)

        const int b  = tile >> 5;             // 32 tiles per batch
        const int i0 = (tile & 31) << 7;      // i base (128-wide tile)
        const int i  = i0 + iw * 32 + lane;   // this thread's output token

        // s-window for this tile: [i0-256, i0+384), 640 values = 8*2*40
        const int s_start = i0 - HALF + split * 80 + sg * 40;

        const float* __restrict__ mrow = mask + b * Sc;
        float acc = 0.0f;

        #pragma unroll 1
        for (int t = 0; t < 40; ++t) {
            const int s = s_start + t;
            if (s < 0 || s >= Sc) continue;
            const int c = Gc + HALF + i - s;           // column for this i
            if (c < Gc || c >= WGc) continue;          // diagonal band edges
            const float flag = (mrow[s] >= 0.0f) ? 1.0f : 0.0f;
            const float* __restrict__ row =
                probs + (size_t)(b * Sc + s) * Hc * WGc + c;
            float a = 0.0f;
            #pragma unroll
            for (int h = 0; h < Hc; ++h)               // 12 independent loads
                a += row[(size_t)h * WGc];
            acc += flag * a;
        }

        __shared__ float red[2][4][33];
        red[sg][iw][lane] = acc;
        __syncthreads();
        if (sg == 0)                                    // warps 0..3 write
            g_local_part[split * BSc + b * Sc + i] =
                red[0][iw][lane] + red[1][iw][lane];    // plain store
    } else {
        const int idx   = blockIdx.x - N_LOCAL_BLOCKS;  // 0..191
        const int b     = idx / N_GCHUNK;
        const int chunk = idx % N_GCHUNK;
        const int c     = threadIdx.x & 63;
        const int rg    = threadIdx.x >> 6;

        const float* __restrict__ mrow = mask + b * Sc;
        const float* __restrict__ base = probs + (size_t)b * Sc * Hc * WGc;

        float acc = 0.0f;
        const int r0 = chunk * 512;      // rows are (s*H + h), 49152 per batch
        #pragma unroll 8
        for (int r = r0 + rg; r < r0 + 512; r += 4) {
            const int s = r / Hc;
            const float flag = (mrow[s] >= 0.0f) ? 1.0f : 0.0f;
            acc += flag * base[(size_t)r * WGc + c];
        }

        __shared__ float gred[4][64];
        gred[rg][c] = acc;
        __syncthreads();
        if (rg == 0)
            g_glob_part[idx * Gc + c] =
                gred[0][c] + gred[1][c] + gred[2][c] + gred[3][c];
    }
}

// ---------------------------------------------------------------------------
// Fused finalize: partial-sum + global-sum + scatter + max + threshold.
// One block per batch, 1024 threads, vectorized loads (latency-optimized).
// ---------------------------------------------------------------------------
__global__ __launch_bounds__(1024) void finalize_kernel(
    const float* __restrict__ thr_p,
    const void* __restrict__ lbv, const void* __restrict__ liv,
    const void* __restrict__ gbv, const void* __restrict__ giv,
    int n, float* __restrict__ out)
{
    __shared__ float ps[Sc];             // probs_sum for this batch (16 KB)
    __shared__ float gpart[8][Bc * Gc];  // two-stage global-sum reduce (4 KB)
    __shared__ float gs[Bc * Gc];        // final global sums, BOTH batches
    __shared__ float smax[32];
    __shared__ int   is32;

    const int b   = blockIdx.x;
    const int tid = threadIdx.x;
    const int lane = tid & 31, wrp = tid >> 5;

    // 1) sum the 8 local partials -> smem   (8 independent float4 loads)
    {
        float4 a = make_float4(0.f, 0.f, 0.f, 0.f);
        #pragma unroll
        for (int p = 0; p < N_SPLIT; ++p) {
            const float4 v = ((const float4*)(g_local_part + p * BSc + b * Sc))[tid];
            a.x += v.x; a.y += v.y; a.z += v.z; a.w += v.w;
        }
        ((float4*)ps)[tid] = a;
    }

    // 2) two-stage global-partial reduce: 12288 loads spread over 1024 threads
    {
        const int out_idx = tid & 127;        // bb*64 + c
        const int grp     = tid >> 7;         // 0..7, 12 chunks each
        const int bb = out_idx >> 6, c = out_idx & 63;
        float a = 0.0f;
        #pragma unroll
        for (int ch = grp * 12; ch < grp * 12 + 12; ++ch)
            a += g_glob_part[(bb * N_GCHUNK + ch) * Gc + c];
        gpart[grp][out_idx] = a;
    }
    if (tid == 0) is32 = 0;
    __syncthreads();
    if (tid < Bc * Gc) {
        float a = 0.0f;
        #pragma unroll
        for (int g = 0; g < 8; ++g) a += gpart[g][tid];
        gs[tid] = a;
    }

    // 3) parallel dtype detect on glob_i: int32 data viewed as int64 words
    //    yields values outside [0, 2^31). Scan n/2 words (safe either layout).
    if (tid < n / 2) {
        const long long v = ((const long long*)giv)[tid];
        if (v < 0 || v >= (1LL << 31)) atomicOr(&is32, 1);
    }
    __syncthreads();

    // 4) scatter: probs_sum[lb, li] += global_sum[gb, gi]  (duplicates add)
    if (tid < n) {
        int lb, li, gb, gi;
        if (is32) {
            lb = ((const int*)lbv)[tid];
            li = ((const int*)liv)[tid];
            gb = ((const int*)gbv)[tid];
            gi = ((const int*)giv)[tid];
        } else {
            lb = (int)((const long long*)lbv)[tid];
            li = (int)((const long long*)liv)[tid];
            gb = (int)((const long long*)gbv)[tid];
            gi = (int)((const long long*)giv)[tid];
        }
        if (lb == b) atomicAdd(&ps[li], gs[gb * Gc + gi]);
    }
    __syncthreads();

    // 5) per-batch max (4 values/thread, shuffle + smem reduce)
    const float4 v = ((const float4*)ps)[tid];
    float m = fmaxf(fmaxf(v.x, v.y), fmaxf(v.z, v.w));
    #pragma unroll
    for (int off = 16; off >= 1; off >>= 1)
        m = fmaxf(m, __shfl_xor_sync(0xffffffffu, m, off));
    if (lane == 0) smax[wrp] = m;
    __syncthreads();
    if (wrp == 0) {
        float mm = smax[lane];
        #pragma unroll
        for (int off = 16; off >= 1; off >>= 1)
            mm = fmaxf(mm, __shfl_xor_sync(0xffffffffu, mm, off));
        if (lane == 0) smax[0] = mm;
    }
    __syncthreads();
    const float pm  = smax[0];
    const float thr = fmaxf(1e-5f, thr_p[0]);

    // 6) outputs: [ new_attention_mask (B*S) | scores (B*S) ], float4 stores
    {
        const float4 sc = make_float4(v.x / pm, v.y / pm, v.z / pm, v.w / pm);
        float4 mk;
        mk.x = (sc.x < thr) ? -10000.0f : 0.0f;
        mk.y = (sc.y < thr) ? -10000.0f : 0.0f;
        mk.z = (sc.z < thr) ? -10000.0f : 0.0f;
        mk.w = (sc.w < thr) ? -10000.0f : 0.0f;
        ((float4*)(out + b * Sc))[tid]       = mk;
        ((float4*)(out + BSc + b * Sc))[tid] = sc;
    }
}

// ---------------------------------------------------------------------------
// launch — 2 graph nodes, allocation-free.
// Inputs (metadata order): attention_mask f32, attention_probs f32,
// keep_threshold f32[1], max_num_global_attn_indices (unused),
// loc_b, loc_i, glob_b, glob_i.
// ---------------------------------------------------------------------------
extern "C" void kernel_launch(void* const* d_in, const int* in_sizes, int n_in,
                              void* d_out, int out_size)
{
    const float* mask  = (const float*)d_in[0];
    const float* probs = (const float*)d_in[1];
    const float* thr   = (const float*)d_in[2];
    const void*  lb    = d_in[4];
    const void*  li    = d_in[5];
    const void*  gb    = d_in[6];
    const void*  gi    = d_in[7];
    float* out = (float*)d_out;
    const int n_idx = in_sizes[4];

    main_kernel<<<N_LOCAL_BLOCKS + N_GLOBAL_BLOCKS, 256>>>(probs, mask);
    finalize_kernel<<<Bc, 1024>>>(thr, lb, li, gb, gi, n_idx, out);
}

// round 9
// speedup vs baseline: 1.1643x; 1.1643x over previous
#include <cuda_runtime.h>

// Problem constants (fixed by the dataset)
#define Bc   2
#define Sc   4096
#define Hc   12
#define Gc   64
#define Wc   513
#define WGc  577      // G + W
#define HALF 256      // W/2
#define BSc  (Bc * Sc)

#define N_SPLIT         16           // s-splits per 128-wide i-tile
#define N_TILES         (Bc * 32)    // 128-wide i-tiles
#define N_LOCAL_BLOCKS  (N_TILES * N_SPLIT)   // 1024
#define N_GCHUNK        96           // row-chunks per batch for global sums
#define N_GLOBAL_BLOCKS (Bc * N_GCHUNK)       // 192
// total grid = 1216 = 8 * 152 -> exact 8 waves on GB300's 152 SMs

// Scratch (plain stores only -> no init kernel, replay-deterministic)
__device__ float g_local_part[N_SPLIT * BSc];        // per-split local partials
__device__ float g_glob_part[N_GLOBAL_BLOCKS * Gc];  // per-chunk global partials

// ---------------------------------------------------------------------------
// Fused main pass: reads all 227 MB of probs exactly once.
//
// Local role (blocks 0..1023), gather formulation:
//   local_sum[b,i] = sum_{s} sum_h probs[b,s,h, 320+i-s],  c in [64,577)
//   Block owns 128 consecutive i (4 warps side-by-side) -> for each (s,h)
//   the block loads a CONTIGUOUS 512B span (sector overfetch 17/16 instead
//   of 5/4). 16 s-splits keep 1024 local blocks resident for latency hiding.
// Global role (blocks 1024..1215):
//   global_sum[b,c] = sum_{s,h} probs[b,s,h,c], c < 64
// ---------------------------------------------------------------------------
__global__ __launch_bounds__(256) void main_kernel(
    const float* __restrict__ probs, const float* __restrict__ mask)
{
    if (blockIdx.x < N_LOCAL_BLOCKS) {
        const int tile  = blockIdx.x >> 4;    // 0..63
        const int split = blockIdx.x & 15;    // 0..15
        const int w     = threadIdx.x >> 5;   // 0..7
        const int lane  = threadIdx.x & 31;
        const int iw    = w & 3;              // i-subtile within block
        const int sg    = w >> 2;             // s-subgroup (0,1)

        const int b  = tile >> 5;             // 32 tiles per batch
        const int i0 = (tile & 31) << 7;      // i base (128-wide tile)
        const int i  = i0 + iw * 32 + lane;   // this thread's output token

        // s-window for this tile: [i0-256, i0+384), 640 values = 16*2*20
        const int s_start = i0 - HALF + split * 40 + sg * 20;

        const float* __restrict__ mrow = mask + b * Sc;
        float acc = 0.0f;

        #pragma unroll 1
        for (int t = 0; t < 20; ++t) {
            const int s = s_start + t;
            if (s < 0 || s >= Sc) continue;
            const int c = Gc + HALF + i - s;           // column for this i
            if (c < Gc || c >= WGc) continue;          // diagonal band edges
            const float flag = (mrow[s] >= 0.0f) ? 1.0f : 0.0f;
            const float* __restrict__ row =
                probs + (size_t)(b * Sc + s) * Hc * WGc + c;
            float a = 0.0f;
            #pragma unroll
            for (int h = 0; h < Hc; ++h)               // 12 independent loads
                a += row[(size_t)h * WGc];
            acc += flag * a;
        }

        __shared__ float red[2][4][33];
        red[sg][iw][lane] = acc;
        __syncthreads();
        if (sg == 0)                                    // warps 0..3 write
            g_local_part[split * BSc + b * Sc + i] =
                red[0][iw][lane] + red[1][iw][lane];    // plain store
    } else {
        const int idx   = blockIdx.x - N_LOCAL_BLOCKS;  // 0..191
        const int b     = idx / N_GCHUNK;
        const int chunk = idx % N_GCHUNK;
        const int c     = threadIdx.x & 63;
        const int rg    = threadIdx.x >> 6;

        const float* __restrict__ mrow = mask + b * Sc;
        const float* __restrict__ base = probs + (size_t)b * Sc * Hc * WGc;

        float acc = 0.0f;
        const int r0 = chunk * 512;      // rows are (s*H + h), 49152 per batch
        #pragma unroll 8
        for (int r = r0 + rg; r < r0 + 512; r += 4) {
            const int s = r / Hc;
            const float flag = (mrow[s] >= 0.0f) ? 1.0f : 0.0f;
            acc += flag * base[(size_t)r * WGc + c];
        }

        __shared__ float gred[4][64];
        gred[rg][c] = acc;
        __syncthreads();
        if (rg == 0)
            g_glob_part[idx * Gc + c] =
                gred[0][c] + gred[1][c] + gred[2][c] + gred[3][c];
    }
}

// ---------------------------------------------------------------------------
// Fused finalize: partial-sum + global-sum + scatter + max + threshold.
// One block per batch, 1024 threads, vectorized loads (latency-optimized).
// ---------------------------------------------------------------------------
__global__ __launch_bounds__(1024) void finalize_kernel(
    const float* __restrict__ thr_p,
    const void* __restrict__ lbv, const void* __restrict__ liv,
    const void* __restrict__ gbv, const void* __restrict__ giv,
    int n, float* __restrict__ out)
{
    __shared__ float ps[Sc];             // probs_sum for this batch (16 KB)
    __shared__ float gpart[8][Bc * Gc];  // two-stage global-sum reduce (4 KB)
    __shared__ float gs[Bc * Gc];        // final global sums, BOTH batches
    __shared__ float smax[32];
    __shared__ int   is32;

    const int b   = blockIdx.x;
    const int tid = threadIdx.x;
    const int lane = tid & 31, wrp = tid >> 5;

    // 1) sum the 16 local partials -> smem  (16 independent float4 loads)
    {
        float4 a = make_float4(0.f, 0.f, 0.f, 0.f);
        #pragma unroll
        for (int p = 0; p < N_SPLIT; ++p) {
            const float4 v = ((const float4*)(g_local_part + p * BSc + b * Sc))[tid];
            a.x += v.x; a.y += v.y; a.z += v.z; a.w += v.w;
        }
        ((float4*)ps)[tid] = a;
    }

    // 2) two-stage global-partial reduce: 12288 loads spread over 1024 threads
    {
        const int out_idx = tid & 127;        // bb*64 + c
        const int grp     = tid >> 7;         // 0..7, 12 chunks each
        const int bb = out_idx >> 6, c = out_idx & 63;
        float a = 0.0f;
        #pragma unroll
        for (int ch = grp * 12; ch < grp * 12 + 12; ++ch)
            a += g_glob_part[(bb * N_GCHUNK + ch) * Gc + c];
        gpart[grp][out_idx] = a;
    }
    if (tid == 0) is32 = 0;
    __syncthreads();
    if (tid < Bc * Gc) {
        float a = 0.0f;
        #pragma unroll
        for (int g = 0; g < 8; ++g) a += gpart[g][tid];
        gs[tid] = a;
    }

    // 3) parallel dtype detect on glob_i: int32 data viewed as int64 words
    //    yields values outside [0, 2^31). Scan n/2 words (safe either layout).
    if (tid < n / 2) {
        const long long v = ((const long long*)giv)[tid];
        if (v < 0 || v >= (1LL << 31)) atomicOr(&is32, 1);
    }
    __syncthreads();

    // 4) scatter: probs_sum[lb, li] += global_sum[gb, gi]  (duplicates add)
    if (tid < n) {
        int lb, li, gb, gi;
        if (is32) {
            lb = ((const int*)lbv)[tid];
            li = ((const int*)liv)[tid];
            gb = ((const int*)gbv)[tid];
            gi = ((const int*)giv)[tid];
        } else {
            lb = (int)((const long long*)lbv)[tid];
            li = (int)((const long long*)liv)[tid];
            gb = (int)((const long long*)gbv)[tid];
            gi = (int)((const long long*)giv)[tid];
        }
        if (lb == b) atomicAdd(&ps[li], gs[gb * Gc + gi]);
    }
    __syncthreads();

    // 5) per-batch max (4 values/thread, shuffle + smem reduce)
    const float4 v = ((const float4*)ps)[tid];
    float m = fmaxf(fmaxf(v.x, v.y), fmaxf(v.z, v.w));
    #pragma unroll
    for (int off = 16; off >= 1; off >>= 1)
        m = fmaxf(m, __shfl_xor_sync(0xffffffffu, m, off));
    if (lane == 0) smax[wrp] = m;
    __syncthreads();
    if (wrp == 0) {
        float mm = smax[lane];
        #pragma unroll
        for (int off = 16; off >= 1; off >>= 1)
            mm = fmaxf(mm, __shfl_xor_sync(0xffffffffu, mm, off));
        if (lane == 0) smax[0] = mm;
    }
    __syncthreads();
    const float pm  = smax[0];
    const float thr = fmaxf(1e-5f, thr_p[0]);

    // 6) outputs: [ new_attention_mask (B*S) | scores (B*S) ], float4 stores
    {
        const float4 sc = make_float4(v.x / pm, v.y / pm, v.z / pm, v.w / pm);
        float4 mk;
        mk.x = (sc.x < thr) ? -10000.0f : 0.0f;
        mk.y = (sc.y < thr) ? -10000.0f : 0.0f;
        mk.z = (sc.z < thr) ? -10000.0f : 0.0f;
        mk.w = (sc.w < thr) ? -10000.0f : 0.0f;
        ((float4*)(out + b * Sc))[tid]       = mk;
        ((float4*)(out + BSc + b * Sc))[tid] = sc;
    }
}

// ---------------------------------------------------------------------------
// launch — 2 graph nodes, allocation-free.
// Inputs (metadata order): attention_mask f32, attention_probs f32,
// keep_threshold f32[1], max_num_global_attn_indices (unused),
// loc_b, loc_i, glob_b, glob_i.
// ---------------------------------------------------------------------------
extern "C" void kernel_launch(void* const* d_in, const int* in_sizes, int n_in,
                              void* d_out, int out_size)
{
    const float* mask  = (const float*)d_in[0];
    const float* probs = (const float*)d_in[1];
    const float* thr   = (const float*)d_in[2];
    const void*  lb    = d_in[4];
    const void*  li    = d_in[5];
    const void*  gb    = d_in[6];
    const void*  gi    = d_in[7];
    float* out = (float*)d_out;
    const int n_idx = in_sizes[4];

    main_kernel<<<N_LOCAL_BLOCKS + N_GLOBAL_BLOCKS, 256>>>(probs, mask);
    finalize_kernel<<<Bc, 1024>>>(thr, lb, li, gb, gi, n_idx, out);
}